// round 1
// baseline (speedup 1.0000x reference)
#include <cuda_runtime.h>
#include <cuda_bf16.h>
#include <cstdint>

#define BATCH 4096
#define DIM   512
#define HIDN  2048
#define NSTEPS 20

// ---------------- persistent scratch (no allocations allowed) ----------------
__device__ float          g_zcur[BATCH*DIM];     // fp32 master state z_i
__device__ float          g_zacc[BATCH*DIM];     // RK4 accumulator
__device__ __nv_bfloat16  g_zb[BATCH*DIM];       // bf16 stage input to GEMM1
__device__ __nv_bfloat16  g_hid[BATCH*HIDN];     // bf16 hidden activations
__device__ __nv_bfloat16  g_w1t[HIDN*DIM];       // W1[:512]^T  [n][k]
__device__ float          g_w1last[HIDN];        // W1[512,:] (time row), fp32
__device__ __nv_bfloat16  g_w2t[DIM*HIDN];       // W2^T [n][k]

// ---------------- converts -----------------
__global__ void convert_z(const float* __restrict__ z0){
    int i = blockIdx.x*blockDim.x + threadIdx.x;
    if (i < BATCH*DIM){
        float v = z0[i];
        g_zcur[i] = v;
        g_zb[i]   = __float2bfloat16(v);
    }
}

__global__ void convert_w(const float* __restrict__ W1, const float* __restrict__ W2){
    int i = blockIdx.x*blockDim.x + threadIdx.x;
    if (i < HIDN*DIM){
        int n = i / DIM, k = i % DIM;
        g_w1t[i] = __float2bfloat16(W1[(size_t)k*HIDN + n]);
    }
    if (i < DIM*HIDN){
        int n = i / HIDN, k = i % HIDN;
        g_w2t[i] = __float2bfloat16(W2[(size_t)k*DIM + n]);
    }
    if (i < HIDN) g_w1last[i] = W1[(size_t)DIM*HIDN + i];
}

// ---------------- fused GEMM ----------------
#define BM 128
#define BN 128
#define BK 32
#define SPAD 40   // smem row stride in bf16 elems (conflict-avoiding)

__device__ __forceinline__ void cpa16(uint32_t s, const void* g){
    asm volatile("cp.async.cg.shared.global [%0], [%1], 16;\n" :: "r"(s), "l"(g));
}

// epi==0: hidden = tanh(zb @ W1t + b1 + t*w1last) -> g_hid (bf16)
// epi==1: k = hid @ W2t + b2 ; RK4 bookkeeping on zcur/zacc/zb/(dout)
__global__ void __launch_bounds__(256)
gemm_fused(const float* __restrict__ b1, const float* __restrict__ b2,
           const float* __restrict__ t0p, const float* __restrict__ t1p,
           float* __restrict__ dout,
           int epi, float stepF, float cOff,
           float wcoef, float acoef, int accPrev, int finalStage, int toOut)
{
    __shared__ __nv_bfloat16 As[2][BM*SPAD];
    __shared__ __nv_bfloat16 Bs[2][BN*SPAD];
    __shared__ float biasS[BN];

    const int tid = threadIdx.x;
    const int bm  = blockIdx.y * BM;
    const int bn  = blockIdx.x * BN;

    const __nv_bfloat16* A; const __nv_bfloat16* B; int Kd; int ldo;
    if (epi == 0){ A = g_zb;  B = g_w1t; Kd = DIM;  ldo = HIDN; }
    else         { A = g_hid; B = g_w2t; Kd = HIDN; ldo = DIM;  }

    const float t0v = __ldg(t0p), t1v = __ldg(t1p);
    const float hh  = (t1v - t0v) / (float)NSTEPS;

    auto loadTile = [&](int buf, int kt){
        const int k0 = kt * BK;
        #pragma unroll
        for (int rep = 0; rep < 2; rep++){
            int v = tid + rep*256;          // 512 16B vectors per operand tile
            int r = v >> 2, c = v & 3;
            uint32_t sA = (uint32_t)__cvta_generic_to_shared(&As[buf][r*SPAD + c*8]);
            cpa16(sA, A + (size_t)(bm + r)*Kd + k0 + c*8);
            uint32_t sB = (uint32_t)__cvta_generic_to_shared(&Bs[buf][r*SPAD + c*8]);
            cpa16(sB, B + (size_t)(bn + r)*Kd + k0 + c*8);
        }
    };

    loadTile(0, 0);
    asm volatile("cp.async.commit_group;\n");

    if (tid < BN){
        float bias;
        if (epi == 0){
            float t = t0v + (stepF + cOff) * hh;
            bias = __ldg(&b1[bn + tid]) + t * g_w1last[bn + tid];
        } else {
            bias = __ldg(&b2[bn + tid]);
        }
        biasS[tid] = bias;
    }

    const int w    = tid >> 5;
    const int lane = tid & 31;
    const int wm   = (w >> 2) * 64;   // 2 warps along M
    const int wn   = (w & 3)  * 32;   // 4 warps along N
    const int g    = lane >> 2;
    const int tq   = lane & 3;

    float acc[4][4][4];
    #pragma unroll
    for (int a=0;a<4;a++)
        #pragma unroll
        for (int b=0;b<4;b++)
            #pragma unroll
            for (int c=0;c<4;c++) acc[a][b][c] = 0.f;

    const int NT = Kd / BK;
    asm volatile("cp.async.wait_group 0;\n");
    __syncthreads();

    for (int kt = 0; kt < NT; kt++){
        const int cur = kt & 1;
        if (kt + 1 < NT){
            loadTile(cur ^ 1, kt + 1);
            asm volatile("cp.async.commit_group;\n");
        }
        #pragma unroll
        for (int kk = 0; kk < BK; kk += 16){
            uint32_t af[4][4];
            #pragma unroll
            for (int mi = 0; mi < 4; mi++){
                const __nv_bfloat16* base0 = &As[cur][(wm + mi*16 + g)*SPAD + kk + tq*2];
                const __nv_bfloat16* base1 = base0 + 8*SPAD;
                af[mi][0] = *(const uint32_t*)(base0);
                af[mi][1] = *(const uint32_t*)(base1);
                af[mi][2] = *(const uint32_t*)(base0 + 8);
                af[mi][3] = *(const uint32_t*)(base1 + 8);
            }
            uint32_t bfr[4][2];
            #pragma unroll
            for (int ni = 0; ni < 4; ni++){
                const __nv_bfloat16* bb = &Bs[cur][(wn + ni*8 + g)*SPAD + kk + tq*2];
                bfr[ni][0] = *(const uint32_t*)(bb);
                bfr[ni][1] = *(const uint32_t*)(bb + 8);
            }
            #pragma unroll
            for (int mi = 0; mi < 4; mi++)
                #pragma unroll
                for (int ni = 0; ni < 4; ni++){
                    asm volatile(
                        "mma.sync.aligned.m16n8k16.row.col.f32.bf16.bf16.f32 "
                        "{%0,%1,%2,%3}, {%4,%5,%6,%7}, {%8,%9}, {%0,%1,%2,%3};\n"
                        : "+f"(acc[mi][ni][0]), "+f"(acc[mi][ni][1]),
                          "+f"(acc[mi][ni][2]), "+f"(acc[mi][ni][3])
                        : "r"(af[mi][0]), "r"(af[mi][1]), "r"(af[mi][2]), "r"(af[mi][3]),
                          "r"(bfr[ni][0]), "r"(bfr[ni][1]));
                }
        }
        if (kt + 1 < NT){
            asm volatile("cp.async.wait_group 0;\n");
            __syncthreads();
        }
    }

    // ------------- epilogue -------------
    const float wh = wcoef * hh;
    const float ah = acoef * hh;
    #pragma unroll
    for (int mi = 0; mi < 4; mi++){
        #pragma unroll
        for (int ni = 0; ni < 4; ni++){
            const int colL = wn + ni*8 + tq*2;
            const int col  = bn + colL;
            #pragma unroll
            for (int half = 0; half < 2; half++){
                const int row = bm + wm + mi*16 + g + half*8;
                float v0 = acc[mi][ni][half*2+0] + biasS[colL];
                float v1 = acc[mi][ni][half*2+1] + biasS[colL+1];
                const size_t idx = (size_t)row * ldo + col;
                if (epi == 0){
                    float th0, th1;
                    asm("tanh.approx.f32 %0, %1;" : "=f"(th0) : "f"(v0));
                    asm("tanh.approx.f32 %0, %1;" : "=f"(th1) : "f"(v1));
                    *(__nv_bfloat162*)(&g_hid[idx]) = __floats2bfloat162_rn(th0, th1);
                } else {
                    const float zc0 = g_zcur[idx], zc1 = g_zcur[idx+1];
                    float za0 = accPrev ? g_zacc[idx]   : 0.f;
                    float za1 = accPrev ? g_zacc[idx+1] : 0.f;
                    za0 += wh * v0;  za1 += wh * v1;
                    g_zacc[idx]   = za0;
                    g_zacc[idx+1] = za1;
                    float zn0, zn1;
                    if (finalStage){ zn0 = zc0 + za0; zn1 = zc1 + za1; }
                    else           { zn0 = zc0 + ah*v0; zn1 = zc1 + ah*v1; }
                    if (finalStage){
                        if (toOut){ dout[idx] = zn0; dout[idx+1] = zn1; }
                        else      { g_zcur[idx] = zn0; g_zcur[idx+1] = zn1; }
                    }
                    *(__nv_bfloat162*)(&g_zb[idx]) = __floats2bfloat162_rn(zn0, zn1);
                }
            }
        }
    }
}

// ---------------- launcher ----------------
extern "C" void kernel_launch(void* const* d_in, const int* in_sizes, int n_in,
                              void* d_out, int out_size)
{
    const float* z0 = (const float*)d_in[0];
    const float* W1 = (const float*)d_in[1];
    const float* b1 = (const float*)d_in[2];
    const float* W2 = (const float*)d_in[3];
    const float* b2 = (const float*)d_in[4];
    const float* t0 = (const float*)d_in[5];
    const float* t1 = (const float*)d_in[6];
    float* dout = (float*)d_out;
    (void)in_sizes; (void)n_in; (void)out_size;

    convert_z<<<(BATCH*DIM + 255)/256, 256>>>(z0);
    convert_w<<<(HIDN*DIM + 255)/256, 256>>>(W1, W2);

    dim3 blk(256);
    dim3 gH(HIDN/BN, BATCH/BM);   // 16 x 32 = 512 CTAs
    dim3 gK(DIM/BN,  BATCH/BM);   //  4 x 32 = 128 CTAs

    const float Wc[4]   = {1.f/6.f, 1.f/3.f, 1.f/3.f, 1.f/6.f};
    const float Ac[4]   = {0.5f, 0.5f, 1.0f, 0.f};
    const float Coff[4] = {0.f, 0.5f, 0.5f, 1.0f};

    for (int i = 0; i < NSTEPS; i++){
        for (int s = 0; s < 4; s++){
            gemm_fused<<<gH, blk>>>(b1, b2, t0, t1, dout,
                                    0, (float)i, Coff[s],
                                    0.f, 0.f, 0, 0, 0);
            const int fin  = (s == 3);
            const int tOut = (fin && i == NSTEPS-1);
            gemm_fused<<<gK, blk>>>(b1, b2, t0, t1, dout,
                                    1, (float)i, 0.f,
                                    Wc[s], Ac[s], (s > 0), fin, tOut);
        }
    }
}

// round 3
// speedup vs baseline: 1.1952x; 1.1952x over previous
#include <cuda_runtime.h>
#include <cuda_bf16.h>
#include <cstdint>

#define BATCH 4096
#define DIM   512
#define HIDN  2048
#define NSTEPS 20

#define BN  128
#define BK  64
#define SPITCH 72         // bf16 elems per smem row (144 B) — LDSM conflict-free
#define ROWB (SPITCH*2)   // 144 bytes

// ---------------- persistent scratch ----------------
__device__ __align__(256) float          g_zcur[BATCH*DIM];
__device__ __align__(256) float          g_zacc[BATCH*DIM];
__device__ __align__(256) __nv_bfloat16  g_zb[BATCH*DIM];
__device__ __align__(256) __nv_bfloat16  g_hid[BATCH*HIDN];
__device__ __align__(256) __nv_bfloat16  g_w1t[HIDN*DIM];    // [n][k]
__device__ __align__(256) float          g_w1last[HIDN];
__device__ __align__(256) __nv_bfloat16  g_w2t[DIM*HIDN];    // [n][k]

// ---------------- converts ----------------
__global__ void convert_z(const float* __restrict__ z0){
    int i = blockIdx.x*blockDim.x + threadIdx.x;
    if (i < BATCH*DIM){
        float v = z0[i];
        g_zcur[i] = v;
        g_zb[i]   = __float2bfloat16(v);
    }
}
__global__ void convert_w(const float* __restrict__ W1, const float* __restrict__ W2){
    int i = blockIdx.x*blockDim.x + threadIdx.x;
    if (i < HIDN*DIM){
        int n = i / DIM, k = i % DIM;
        g_w1t[i] = __float2bfloat16(W1[(size_t)k*HIDN + n]);
    }
    if (i < DIM*HIDN){
        int n = i / HIDN, k = i % HIDN;
        g_w2t[i] = __float2bfloat16(W2[(size_t)k*DIM + n]);
    }
    if (i < HIDN) g_w1last[i] = W1[(size_t)DIM*HIDN + i];
}

// ---------------- helpers ----------------
__device__ __forceinline__ void cpa16(uint32_t s, const void* g){
    asm volatile("cp.async.cg.shared.global [%0], [%1], 16;\n" :: "r"(s), "l"(g));
}
__device__ __forceinline__ void ldsm4(uint32_t& r0, uint32_t& r1, uint32_t& r2, uint32_t& r3,
                                      uint32_t addr){
    asm volatile("ldmatrix.sync.aligned.m8n8.x4.shared.b16 {%0,%1,%2,%3}, [%4];"
                 : "=r"(r0), "=r"(r1), "=r"(r2), "=r"(r3) : "r"(addr));
}
__device__ __forceinline__ uint32_t smem_u32(const void* p){
    uint32_t a;
    asm("{ .reg .u64 t; cvta.to.shared.u64 t, %1; cvt.u32.u64 %0, t; }" : "=r"(a) : "l"(p));
    return a;
}

// ---------------- fused GEMM (mma.sync + ldmatrix, 2-stage cp.async) ----------------
// epi==0: g_hid = tanh(g_zb @ g_w1t^T + b1 + t*w1last)  [4096 x 2048], K=512
// epi==1: k = g_hid @ g_w2t^T + b2 ; RK4 update         [4096 x 512],  K=2048
template<int BM, int MI>   // warp tile = (BM/2) x 32 ; MI = BM/32
__global__ void __launch_bounds__(256, 2)
gemm_tc(const float* __restrict__ b1, const float* __restrict__ b2,
        const float* __restrict__ t0p, const float* __restrict__ t1p,
        float* __restrict__ dout,
        int epi, float stepF, float cOff,
        float wcoef, float acoef, int accPrev, int finalStage, int toOut)
{
    constexpr int ASZ = BM * ROWB;       // per-stage A bytes
    constexpr int BSZ = BN * ROWB;       // per-stage B bytes
    constexpr int SM_A = 1024;
    constexpr int SM_B = SM_A + 2*ASZ;

    extern __shared__ char smem[];
    const uint32_t sb = smem_u32(smem);
    float* biasS = (float*)smem;

    const int tid  = threadIdx.x;
    const int lane = tid & 31, w = tid >> 5;
    const int bm = blockIdx.y * BM, bn = blockIdx.x * BN;

    const __nv_bfloat16* A; const __nv_bfloat16* B; int Kd, ldo;
    if (epi == 0){ A = g_zb;  B = g_w1t; Kd = DIM;  ldo = HIDN; }
    else         { A = g_hid; B = g_w2t; Kd = HIDN; ldo = DIM;  }
    const int NT = Kd / BK;

    // warp tiling: 2 warps along M, 4 along N
    const int wm = (w >> 2) * (BM/2);
    const int wn = (w & 3)  * 32;

    // ldmatrix lane address components
    const int lr = lane & 7;
    const int lm = (lane >> 3) & 1;
    const int lk = (lane >> 3) >> 1;
    const uint32_t aBase = sb + SM_A + (uint32_t)((wm + lr + lm*8)*SPITCH + lk*8)*2;
    const uint32_t bBase = sb + SM_B + (uint32_t)((wn + lr + lm*8)*SPITCH + lk*8)*2;

    auto loadChunk = [&](int c){
        const int s  = c & 1;
        const int k0 = c * BK;
        const uint32_t sA = sb + SM_A + s*ASZ;
        const uint32_t sB = sb + SM_B + s*BSZ;
        #pragma unroll
        for (int r = 0; r < BM*8/256; r++){
            int v = tid + r*256;
            int row = v >> 3, col = v & 7;
            cpa16(sA + row*ROWB + col*16, A + (size_t)(bm + row)*Kd + k0 + col*8);
        }
        #pragma unroll
        for (int r = 0; r < 4; r++){
            int v = tid + r*256;
            int row = v >> 3, col = v & 7;
            cpa16(sB + row*ROWB + col*16, B + (size_t)(bn + row)*Kd + k0 + col*8);
        }
        asm volatile("cp.async.commit_group;\n");
    };

    loadChunk(0);
    loadChunk(1);

    // bias -> smem
    const float t0v = __ldg(t0p), t1v = __ldg(t1p);
    const float hh  = (t1v - t0v) / (float)NSTEPS;
    if (tid < BN){
        float bias;
        if (epi == 0){
            float t = t0v + (stepF + cOff) * hh;
            bias = __ldg(&b1[bn + tid]) + t * g_w1last[bn + tid];
        } else bias = __ldg(&b2[bn + tid]);
        biasS[tid] = bias;
    }

    float acc[MI][4][4];
    #pragma unroll
    for (int a=0;a<MI;a++)
        #pragma unroll
        for (int b=0;b<4;b++)
            #pragma unroll
            for (int c=0;c<4;c++) acc[a][b][c] = 0.f;

    for (int kt = 0; kt < NT; kt++){
        if (kt < NT-1) asm volatile("cp.async.wait_group 1;\n");
        else           asm volatile("cp.async.wait_group 0;\n");
        __syncthreads();

        const int s = kt & 1;
        const uint32_t aAddr = aBase + s*ASZ;
        const uint32_t bAddr = bBase + s*BSZ;

        #pragma unroll
        for (int kk = 0; kk < BK; kk += 16){
            uint32_t af[MI][4];
            #pragma unroll
            for (int mi = 0; mi < MI; mi++)
                ldsm4(af[mi][0], af[mi][1], af[mi][2], af[mi][3],
                      aAddr + (uint32_t)(mi*16*ROWB) + kk*2);
            uint32_t bfr[4][2];
            #pragma unroll
            for (int nh = 0; nh < 2; nh++){
                uint32_t r0, r1, r2, r3;
                ldsm4(r0, r1, r2, r3, bAddr + (uint32_t)(nh*16*ROWB) + kk*2);
                bfr[2*nh  ][0] = r0; bfr[2*nh  ][1] = r2;
                bfr[2*nh+1][0] = r1; bfr[2*nh+1][1] = r3;
            }
            #pragma unroll
            for (int mi = 0; mi < MI; mi++)
                #pragma unroll
                for (int ni = 0; ni < 4; ni++){
                    asm volatile(
                        "mma.sync.aligned.m16n8k16.row.col.f32.bf16.bf16.f32 "
                        "{%0,%1,%2,%3}, {%4,%5,%6,%7}, {%8,%9}, {%0,%1,%2,%3};\n"
                        : "+f"(acc[mi][ni][0]), "+f"(acc[mi][ni][1]),
                          "+f"(acc[mi][ni][2]), "+f"(acc[mi][ni][3])
                        : "r"(af[mi][0]), "r"(af[mi][1]), "r"(af[mi][2]), "r"(af[mi][3]),
                          "r"(bfr[ni][0]), "r"(bfr[ni][1]));
                }
        }
        __syncthreads();
        if (kt + 2 < NT) loadChunk(kt + 2);
    }

    // ---------------- epilogue ----------------
    const int g  = lane >> 2;
    const int tq = lane & 3;
    const float wh = wcoef * hh;
    const float ah = acoef * hh;

    #pragma unroll
    for (int mi = 0; mi < MI; mi++){
        #pragma unroll
        for (int ni = 0; ni < 4; ni++){
            const int colL = wn + ni*8 + tq*2;
            const int col  = bn + colL;
            #pragma unroll
            for (int half = 0; half < 2; half++){
                const int row = bm + wm + mi*16 + g + half*8;
                float v0 = acc[mi][ni][half*2+0] + biasS[colL];
                float v1 = acc[mi][ni][half*2+1] + biasS[colL+1];
                const size_t idx = (size_t)row * ldo + col;
                if (epi == 0){
                    float th0, th1;
                    asm("tanh.approx.f32 %0, %1;" : "=f"(th0) : "f"(v0));
                    asm("tanh.approx.f32 %0, %1;" : "=f"(th1) : "f"(v1));
                    *(__nv_bfloat162*)(&g_hid[idx]) = __floats2bfloat162_rn(th0, th1);
                } else {
                    const float zc0 = g_zcur[idx], zc1 = g_zcur[idx+1];
                    float za0 = accPrev ? g_zacc[idx]   : 0.f;
                    float za1 = accPrev ? g_zacc[idx+1] : 0.f;
                    za0 += wh * v0;  za1 += wh * v1;
                    g_zacc[idx]   = za0;
                    g_zacc[idx+1] = za1;
                    float zn0, zn1;
                    if (finalStage){
                        zn0 = zc0 + za0; zn1 = zc1 + za1;
                        if (toOut){ dout[idx] = zn0; dout[idx+1] = zn1; }
                        else      { g_zcur[idx] = zn0; g_zcur[idx+1] = zn1; }
                    } else {
                        zn0 = zc0 + ah*v0; zn1 = zc1 + ah*v1;
                    }
                    *(__nv_bfloat162*)(&g_zb[idx]) = __floats2bfloat162_rn(zn0, zn1);
                }
            }
        }
    }
}

// ---------------- launcher ----------------
extern "C" void kernel_launch(void* const* d_in, const int* in_sizes, int n_in,
                              void* d_out, int out_size)
{
    const float* z0 = (const float*)d_in[0];
    const float* W1 = (const float*)d_in[1];
    const float* b1 = (const float*)d_in[2];
    const float* W2 = (const float*)d_in[3];
    const float* b2 = (const float*)d_in[4];
    const float* t0 = (const float*)d_in[5];
    const float* t1 = (const float*)d_in[6];
    float* dout = (float*)d_out;
    (void)in_sizes; (void)n_in; (void)out_size;

    constexpr int SMEM1 = 1024 + 2*(128*ROWB) + 2*(BN*ROWB);  // 74752
    constexpr int SMEM2 = 1024 + 2*( 64*ROWB) + 2*(BN*ROWB);  // 56320

    cudaFuncSetAttribute(gemm_tc<128,4>, cudaFuncAttributeMaxDynamicSharedMemorySize, SMEM1);
    cudaFuncSetAttribute(gemm_tc<64,2>,  cudaFuncAttributeMaxDynamicSharedMemorySize, SMEM2);

    convert_z<<<(BATCH*DIM + 255)/256, 256>>>(z0);
    convert_w<<<(HIDN*DIM + 255)/256, 256>>>(W1, W2);

    dim3 gH(HIDN/BN, BATCH/128);   // 16 x 32 = 512 CTAs
    dim3 gK(DIM/BN,  BATCH/64);    //  4 x 64 = 256 CTAs

    const float Wc[4]   = {1.f/6.f, 1.f/3.f, 1.f/3.f, 1.f/6.f};
    const float Ac[4]   = {0.5f, 0.5f, 1.0f, 0.f};
    const float Coff[4] = {0.f, 0.5f, 0.5f, 1.0f};

    for (int i = 0; i < NSTEPS; i++){
        for (int s = 0; s < 4; s++){
            gemm_tc<128,4><<<gH, 256, SMEM1>>>(b1, b2, t0, t1, dout,
                                               0, (float)i, Coff[s],
                                               0.f, 0.f, 0, 0, 0);
            const int fin  = (s == 3);
            const int tOut = (fin && i == NSTEPS-1);
            gemm_tc<64,2><<<gK, 256, SMEM2>>>(b1, b2, t0, t1, dout,
                                              1, (float)i, 0.f,
                                              Wc[s], Ac[s], (s > 0), fin, tOut);
        }
    }
}

// round 4
// speedup vs baseline: 1.2069x; 1.0098x over previous
#include <cuda_runtime.h>
#include <cuda_bf16.h>
#include <cstdint>

#define BATCH 4096
#define DIM   512
#define HIDN  2048
#define NSTEPS 20

#define BM 64
#define BN 128
#define BK 64
#define SPITCH 72         // bf16 per smem row (144B) — LDSM conflict-free
#define ROWB (SPITCH*2)

#define ASZ (BM*ROWB)
#define BSZ (BN*ROWB)
#define SM_A 1024
#define SM_B (SM_A + 3*ASZ)
#define SMEM_TOT (SM_B + 3*BSZ)

// ---------------- persistent scratch ----------------
__device__ __align__(256) float          g_zcur[BATCH*DIM];
__device__ __align__(256) float          g_zacc[BATCH*DIM];
__device__ __align__(256) __nv_bfloat16  g_zb[BATCH*DIM];
__device__ __align__(256) __nv_bfloat16  g_hid[BATCH*HIDN];
__device__ __align__(256) __nv_bfloat16  g_w1t[HIDN*DIM];    // [n][k]
__device__ __align__(256) float          g_w1last[HIDN];
__device__ __align__(256) __nv_bfloat16  g_w2t[DIM*HIDN];    // [n][k]

// ---------------- converts ----------------
__global__ void convert_z(const float* __restrict__ z0){
    int i = blockIdx.x*blockDim.x + threadIdx.x;
    if (i < BATCH*DIM){
        float v = z0[i];
        g_zcur[i] = v;
        g_zb[i]   = __float2bfloat16(v);
    }
}
__global__ void convert_w(const float* __restrict__ W1, const float* __restrict__ W2){
    int i = blockIdx.x*blockDim.x + threadIdx.x;
    if (i < HIDN*DIM){
        int n = i / DIM, k = i % DIM;
        g_w1t[i] = __float2bfloat16(W1[(size_t)k*HIDN + n]);
    }
    if (i < DIM*HIDN){
        int n = i / HIDN, k = i % HIDN;
        g_w2t[i] = __float2bfloat16(W2[(size_t)k*DIM + n]);
    }
    if (i < HIDN) g_w1last[i] = W1[(size_t)DIM*HIDN + i];
}

// ---------------- helpers ----------------
__device__ __forceinline__ void cpa16(uint32_t s, const void* g){
    asm volatile("cp.async.cg.shared.global [%0], [%1], 16;\n" :: "r"(s), "l"(g));
}
__device__ __forceinline__ void ldsm4(uint32_t& r0, uint32_t& r1, uint32_t& r2, uint32_t& r3,
                                      uint32_t addr){
    asm volatile("ldmatrix.sync.aligned.m8n8.x4.shared.b16 {%0,%1,%2,%3}, [%4];"
                 : "=r"(r0), "=r"(r1), "=r"(r2), "=r"(r3) : "r"(addr));
}
__device__ __forceinline__ uint32_t smem_u32(const void* p){
    uint32_t a;
    asm("{ .reg .u64 t; cvta.to.shared.u64 t, %1; cvt.u32.u64 %0, t; }" : "=r"(a) : "l"(p));
    return a;
}

// ---------------- fused GEMM ----------------
// epi==0: g_hid = tanh(g_zb @ g_w1t^T + b1 + t*w1last)  [4096 x 2048], K=512
// epi==1: k = g_hid @ g_w2t^T + b2 ; RK4 update         [4096 x 512],  K=2048
__global__ void __launch_bounds__(256, 2)
gemm_tc(const float* __restrict__ b1, const float* __restrict__ b2,
        const float* __restrict__ t0p, const float* __restrict__ t1p,
        float* __restrict__ dout,
        int epi, float stepF, float cOff,
        float wcoef, float acoef, int accPrev, int finalStage, int toOut)
{
    extern __shared__ char smem[];
    const uint32_t sb = smem_u32(smem);
    float* biasS = (float*)smem;

    const int tid  = threadIdx.x;
    const int lane = tid & 31, w = tid >> 5;
    const int bm = blockIdx.y * BM, bn = blockIdx.x * BN;

    const __nv_bfloat16* A; const __nv_bfloat16* B; int Kd, ldo;
    if (epi == 0){ A = g_zb;  B = g_w1t; Kd = DIM;  ldo = HIDN; }
    else         { A = g_hid; B = g_w2t; Kd = HIDN; ldo = DIM;  }
    const int NT = Kd / BK;

    // 2 warps along M, 4 along N ; warp tile 32x32
    const int wm = (w >> 2) * 32;
    const int wn = (w & 3)  * 32;

    // ldmatrix lane addressing
    const int lr = lane & 7;
    const int lm = (lane >> 3) & 1;
    const int lk = (lane >> 3) >> 1;
    const uint32_t aBase = sb + SM_A + (uint32_t)((wm + lr + lm*8)*SPITCH + lk*8)*2;
    const uint32_t bBase = sb + SM_B + (uint32_t)((wn + lr + lm*8)*SPITCH + lk*8)*2;

    auto loadChunk = [&](int c){
        const int s  = c % 3;
        const int k0 = c * BK;
        const uint32_t sA = sb + SM_A + s*ASZ;
        const uint32_t sB = sb + SM_B + s*BSZ;
        #pragma unroll
        for (int r = 0; r < 2; r++){                 // A: 64 rows x 8 x 16B
            int v = tid + r*256;
            int row = v >> 3, col = v & 7;
            cpa16(sA + row*ROWB + col*16, A + (size_t)(bm + row)*Kd + k0 + col*8);
        }
        #pragma unroll
        for (int r = 0; r < 4; r++){                 // B: 128 rows x 8 x 16B
            int v = tid + r*256;
            int row = v >> 3, col = v & 7;
            cpa16(sB + row*ROWB + col*16, B + (size_t)(bn + row)*Kd + k0 + col*8);
        }
        asm volatile("cp.async.commit_group;\n");
    };

    loadChunk(0);
    loadChunk(1);

    // bias -> smem
    const float t0v = __ldg(t0p), t1v = __ldg(t1p);
    const float hh  = (t1v - t0v) / (float)NSTEPS;
    if (tid < BN){
        float bias;
        if (epi == 0){
            float t = t0v + (stepF + cOff) * hh;
            bias = __ldg(&b1[bn + tid]) + t * g_w1last[bn + tid];
        } else bias = __ldg(&b2[bn + tid]);
        biasS[tid] = bias;
    }

    float acc[2][4][4];
    #pragma unroll
    for (int a=0;a<2;a++)
        #pragma unroll
        for (int b=0;b<4;b++)
            #pragma unroll
            for (int c=0;c<4;c++) acc[a][b][c] = 0.f;

    uint32_t af[2][2][4];   // [buf][mi][frag]
    uint32_t bf[2][4][2];   // [buf][ni][frag]

    for (int kt = 0; kt < NT; kt++){
        if (kt < NT-1) asm volatile("cp.async.wait_group 1;\n");
        else           asm volatile("cp.async.wait_group 0;\n");
        __syncthreads();
        if (kt + 2 < NT) loadChunk(kt + 2);

        const int s = kt % 3;
        const uint32_t aAddr = aBase + s*ASZ;
        const uint32_t bAddr = bBase + s*BSZ;

        // prefetch kk = 0
        #pragma unroll
        for (int mi = 0; mi < 2; mi++)
            ldsm4(af[0][mi][0], af[0][mi][1], af[0][mi][2], af[0][mi][3],
                  aAddr + (uint32_t)(mi*16*ROWB));
        #pragma unroll
        for (int nh = 0; nh < 2; nh++){
            uint32_t r0, r1, r2, r3;
            ldsm4(r0, r1, r2, r3, bAddr + (uint32_t)(nh*16*ROWB));
            bf[0][2*nh  ][0] = r0; bf[0][2*nh  ][1] = r2;
            bf[0][2*nh+1][0] = r1; bf[0][2*nh+1][1] = r3;
        }

        #pragma unroll
        for (int kki = 0; kki < 4; kki++){
            const int cur = kki & 1, nxt = cur ^ 1;
            if (kki < 3){
                const uint32_t koff = (uint32_t)((kki+1)*16*2);
                #pragma unroll
                for (int mi = 0; mi < 2; mi++)
                    ldsm4(af[nxt][mi][0], af[nxt][mi][1], af[nxt][mi][2], af[nxt][mi][3],
                          aAddr + (uint32_t)(mi*16*ROWB) + koff);
                #pragma unroll
                for (int nh = 0; nh < 2; nh++){
                    uint32_t r0, r1, r2, r3;
                    ldsm4(r0, r1, r2, r3, bAddr + (uint32_t)(nh*16*ROWB) + koff);
                    bf[nxt][2*nh  ][0] = r0; bf[nxt][2*nh  ][1] = r2;
                    bf[nxt][2*nh+1][0] = r1; bf[nxt][2*nh+1][1] = r3;
                }
            }
            #pragma unroll
            for (int mi = 0; mi < 2; mi++)
                #pragma unroll
                for (int ni = 0; ni < 4; ni++){
                    asm volatile(
                        "mma.sync.aligned.m16n8k16.row.col.f32.bf16.bf16.f32 "
                        "{%0,%1,%2,%3}, {%4,%5,%6,%7}, {%8,%9}, {%0,%1,%2,%3};\n"
                        : "+f"(acc[mi][ni][0]), "+f"(acc[mi][ni][1]),
                          "+f"(acc[mi][ni][2]), "+f"(acc[mi][ni][3])
                        : "r"(af[cur][mi][0]), "r"(af[cur][mi][1]),
                          "r"(af[cur][mi][2]), "r"(af[cur][mi][3]),
                          "r"(bf[cur][ni][0]), "r"(bf[cur][ni][1]));
                }
        }
    }

    // ---------------- epilogue ----------------
    const int g  = lane >> 2;
    const int tq = lane & 3;
    const float wh = wcoef * hh;
    const float ah = acoef * hh;

    #pragma unroll
    for (int mi = 0; mi < 2; mi++){
        #pragma unroll
        for (int ni = 0; ni < 4; ni++){
            const int colL = wn + ni*8 + tq*2;
            const int col  = bn + colL;
            #pragma unroll
            for (int half = 0; half < 2; half++){
                const int row = bm + wm + mi*16 + g + half*8;
                float v0 = acc[mi][ni][half*2+0] + biasS[colL];
                float v1 = acc[mi][ni][half*2+1] + biasS[colL+1];
                const size_t idx = (size_t)row * ldo + col;
                if (epi == 0){
                    float th0, th1;
                    asm("tanh.approx.f32 %0, %1;" : "=f"(th0) : "f"(v0));
                    asm("tanh.approx.f32 %0, %1;" : "=f"(th1) : "f"(v1));
                    *(__nv_bfloat162*)(&g_hid[idx]) = __floats2bfloat162_rn(th0, th1);
                } else {
                    const float zc0 = g_zcur[idx], zc1 = g_zcur[idx+1];
                    float za0 = accPrev ? g_zacc[idx]   : 0.f;
                    float za1 = accPrev ? g_zacc[idx+1] : 0.f;
                    za0 += wh * v0;  za1 += wh * v1;
                    g_zacc[idx]   = za0;
                    g_zacc[idx+1] = za1;
                    float zn0, zn1;
                    if (finalStage){
                        zn0 = zc0 + za0; zn1 = zc1 + za1;
                        if (toOut){ dout[idx] = zn0; dout[idx+1] = zn1; }
                        else      { g_zcur[idx] = zn0; g_zcur[idx+1] = zn1; }
                    } else {
                        zn0 = zc0 + ah*v0; zn1 = zc1 + ah*v1;
                    }
                    *(__nv_bfloat162*)(&g_zb[idx]) = __floats2bfloat162_rn(zn0, zn1);
                }
            }
        }
    }
}

// ---------------- launcher ----------------
extern "C" void kernel_launch(void* const* d_in, const int* in_sizes, int n_in,
                              void* d_out, int out_size)
{
    const float* z0 = (const float*)d_in[0];
    const float* W1 = (const float*)d_in[1];
    const float* b1 = (const float*)d_in[2];
    const float* W2 = (const float*)d_in[3];
    const float* b2 = (const float*)d_in[4];
    const float* t0 = (const float*)d_in[5];
    const float* t1 = (const float*)d_in[6];
    float* dout = (float*)d_out;
    (void)in_sizes; (void)n_in; (void)out_size;

    cudaFuncSetAttribute(gemm_tc, cudaFuncAttributeMaxDynamicSharedMemorySize, SMEM_TOT);

    convert_z<<<(BATCH*DIM + 255)/256, 256>>>(z0);
    convert_w<<<(HIDN*DIM + 255)/256, 256>>>(W1, W2);

    dim3 gH(HIDN/BN, BATCH/BM);   // 16 x 64 = 1024 CTAs
    dim3 gK(DIM/BN,  BATCH/BM);   //  4 x 64 =  256 CTAs

    const float Wc[4]   = {1.f/6.f, 1.f/3.f, 1.f/3.f, 1.f/6.f};
    const float Ac[4]   = {0.5f, 0.5f, 1.0f, 0.f};
    const float Coff[4] = {0.f, 0.5f, 0.5f, 1.0f};

    for (int i = 0; i < NSTEPS; i++){
        for (int s = 0; s < 4; s++){
            gemm_tc<<<gH, 256, SMEM_TOT>>>(b1, b2, t0, t1, dout,
                                           0, (float)i, Coff[s],
                                           0.f, 0.f, 0, 0, 0);
            const int fin  = (s == 3);
            const int tOut = (fin && i == NSTEPS-1);
            gemm_tc<<<gK, 256, SMEM_TOT>>>(b1, b2, t0, t1, dout,
                                           1, (float)i, 0.f,
                                           Wc[s], Ac[s], (s > 0), fin, tOut);
        }
    }
}